// round 11
// baseline (speedup 1.0000x reference)
#include <cuda_runtime.h>

// ---------------------------------------------------------------------------
// StandAloneSelfAttention: 7x7 local attention, B=4, H=W=64, C=128, 8 heads x 16
// K1: QKV GEMM, M=64 tiles, K in two 64-chunks -> 49KB smem, 4 CTAs/SM,
//     256 threads; f32x2-packed FFMA. Load phases overlap across CTAs.
// K2: streaming local attention (unchanged from measured 35.5us version).
// ---------------------------------------------------------------------------

#define IMG 64
#define CH 128
#define HEADS 8
#define HSIZE 16
#define TILE 16
#define HALO 22          // TILE + 6
#define KD 49            // 7*7
#define NPIX (4*IMG*IMG) // 16384

#define XPAD 68          // x_s row stride (floats): 16B-aligned, bank-safe

__device__ float g_qkv[3][NPIX * CH];

typedef unsigned long long ull;

__device__ __forceinline__ ull ffma2(ull a, ull b, ull c) {
    ull d;
    asm("fma.rn.f32x2 %0, %1, %2, %3;" : "=l"(d) : "l"(a), "l"(b), "l"(c));
    return d;
}
__device__ __forceinline__ ull add2(ull a, ull b) {
    ull d;
    asm("add.rn.f32x2 %0, %1, %2;" : "=l"(d) : "l"(a), "l"(b));
    return d;
}
__device__ __forceinline__ ull pack2(float x) {
    ull d;
    asm("mov.b64 %0, {%1, %1};" : "=l"(d) : "f"(x));
    return d;
}
__device__ __forceinline__ void unpack2(ull p, float& lo, float& hi) {
    asm("mov.b64 {%0,%1}, %2;" : "=f"(lo), "=f"(hi) : "l"(p));
}
__device__ __forceinline__ float hsum2(ull a, ull b) {
    float lo, hi;
    unpack2(add2(a, b), lo, hi);
    return lo + hi;
}

// ---------------------------------------------------------------------------
// Kernel 1: out = x @ W + b. M=64 x N=128 tile, K=128 in two 64-chunks.
// 256 threads: tx(0..15) -> 4 n-pairs, ty(0..15) -> 4 m-rows.
// smem ~49KB -> 4 CTAs/SM; grid = (256 m-tiles, 3 matrices).
// ---------------------------------------------------------------------------
__global__ __launch_bounds__(256, 4) void qkv_kernel(
    const float* __restrict__ x,
    const float* __restrict__ Wq, const float* __restrict__ bq,
    const float* __restrict__ Wk, const float* __restrict__ bk,
    const float* __restrict__ Wv, const float* __restrict__ bv)
{
    extern __shared__ float sm[];
    float* x_s = sm;                  // [64][XPAD] (64 cols used)
    float* w_s = sm + 64 * XPAD;      // [64][128] k-major

    const int tid = threadIdx.x;
    const int m0 = blockIdx.x * 64;
    const int w = blockIdx.y;
    const float* W = (w == 0) ? Wq : (w == 1) ? Wk : Wv;
    const float* B = (w == 0) ? bq : (w == 1) ? bk : bv;
    float* out = g_qkv[w];

    const int tx = tid & 15;
    const int ty = tid >> 4;      // 0..15

    ull acc[4][4];
    #pragma unroll
    for (int i = 0; i < 4; i++)
        #pragma unroll
        for (int jj = 0; jj < 4; jj++) acc[i][jj] = 0ULL;

    for (int kc = 0; kc < 2; kc++) {
        // load x chunk: 64 rows x 64 floats = 1024 float4, 4 per thread
        #pragma unroll
        for (int i = 0; i < 4; i++) {
            int idx = tid + i * 256;
            int row = idx >> 4, c4 = idx & 15;
            float4 v = *reinterpret_cast<const float4*>(
                &x[(long)(m0 + row) * CH + kc * 64 + c4 * 4]);
            *reinterpret_cast<float4*>(&x_s[row * XPAD + c4 * 4]) = v;
        }
        // load W chunk: 64 rows x 128 floats = 2048 float4, 8 per thread
        #pragma unroll
        for (int i = 0; i < 8; i++) {
            int idx = tid + i * 256;
            int row = idx >> 5, c4 = idx & 31;
            float4 v = *reinterpret_cast<const float4*>(
                &W[(long)(kc * 64 + row) * 128 + c4 * 4]);
            *reinterpret_cast<float4*>(&w_s[row * 128 + c4 * 4]) = v;
        }
        __syncthreads();

        #pragma unroll 4
        for (int k = 0; k < 64; k++) {
            ull bv_[4];
            #pragma unroll
            for (int jj = 0; jj < 4; jj++)
                bv_[jj] = *reinterpret_cast<const ull*>(
                    &w_s[k * 128 + 2 * tx + 32 * jj]);
            #pragma unroll
            for (int i = 0; i < 4; i++) {
                ull av = pack2(x_s[(ty * 4 + i) * XPAD + k]);  // broadcast
                #pragma unroll
                for (int jj = 0; jj < 4; jj++)
                    acc[i][jj] = ffma2(av, bv_[jj], acc[i][jj]);
            }
        }
        __syncthreads();
    }

    #pragma unroll
    for (int i = 0; i < 4; i++) {
        long gm = m0 + ty * 4 + i;
        #pragma unroll
        for (int jj = 0; jj < 4; jj++) {
            int n = 2 * tx + 32 * jj;
            float lo, hi;
            unpack2(acc[i][jj], lo, hi);
            float2 r;
            r.x = lo + B[n];
            r.y = hi + B[n + 1];
            *reinterpret_cast<float2*>(&out[gm * CH + n]) = r;
        }
    }
}

// ---------------------------------------------------------------------------
// Kernel 2: streaming local attention (unchanged, measured 35.5us).
// 128 threads, 16x16 tile, 2 vertical pixels/thread, no-max softmax,
// fused score+exp+PV, qe7 emb collapse, 3 CTAs/SM.
// ---------------------------------------------------------------------------
__global__ __launch_bounds__(128, 3) void attn_kernel(
    float* __restrict__ out,
    const float* __restrict__ emb0,   // [64, 7]
    const float* __restrict__ emb1)   // [64, 7]
{
    extern __shared__ float4 sm4[];
    float4* k4 = sm4;                       // [4][484]
    float4* v4 = sm4 + 4 * 484;             // [4][484]
    float* es = (float*)(sm4 + 8 * 484);    // [7][16]

    const int tid = threadIdx.x;
    const int head = blockIdx.y;
    const int b = blockIdx.z;
    const int y0 = (blockIdx.x >> 2) * TILE;
    const int x0 = (blockIdx.x & 3) * TILE;

    const float* gq = g_qkv[0];
    const float* gk = g_qkv[1];
    const float* gv = g_qkv[2];

    // --- stage K/V halo (zero pad = reference 'SAME' semantics) ---
    for (int i = tid; i < HALO * HALO; i += 128) {
        int hy = i / HALO, hx = i % HALO;
        int gy = y0 + hy - 3, gx = x0 + hx - 3;
        float4 kk[4], vv[4];
        if ((unsigned)gy < (unsigned)IMG && (unsigned)gx < (unsigned)IMG) {
            long off = (((long)(b * IMG + gy) * IMG + gx) * CH + head * HSIZE);
            const float4* kp = reinterpret_cast<const float4*>(gk + off);
            const float4* vp = reinterpret_cast<const float4*>(gv + off);
            #pragma unroll
            for (int j = 0; j < 4; j++) { kk[j] = kp[j]; vv[j] = vp[j]; }
        } else {
            #pragma unroll
            for (int j = 0; j < 4; j++) {
                kk[j] = make_float4(0.f, 0.f, 0.f, 0.f);
                vv[j] = kk[j];
            }
        }
        #pragma unroll
        for (int j = 0; j < 4; j++) {
            k4[j * 484 + i] = kk[j];
            v4[j * 484 + i] = vv[j];
        }
    }

    // --- stage per-head emb axis table es[a][d], a=0..6 ---
    if (tid < 7 * HSIZE) {
        int a = tid >> 4, d = tid & 15;
        float val = (head < 4) ? emb0[(head * HSIZE + d) * 7 + a]
                               : emb1[((head - 4) * HSIZE + d) * 7 + a];
        es[a * HSIZE + d] = val;
    }
    __syncthreads();

    const int px = tid & 15;
    const int tyy = tid >> 4;            // 0..7
    const int y = y0 + 2 * tyy;
    const long poff0 = (((long)(b * IMG + y) * IMG + (x0 + px)) * CH + head * HSIZE);
    const long poff1 = poff0 + (long)IMG * CH;

    ull q0[8], q1[8];
    {
        const ulonglong2* qp0 = reinterpret_cast<const ulonglong2*>(gq + poff0);
        const ulonglong2* qp1 = reinterpret_cast<const ulonglong2*>(gq + poff1);
        #pragma unroll
        for (int j = 0; j < 4; j++) {
            ulonglong2 t0 = qp0[j];
            ulonglong2 t1 = qp1[j];
            q0[2 * j] = t0.x; q0[2 * j + 1] = t0.y;
            q1[2 * j] = t1.x; q1[2 * j + 1] = t1.y;
        }
    }

    // --- qe7: q . emb_axis[a] ---
    float qe70[7], qe71[7];
    #pragma unroll
    for (int a = 0; a < 7; a++) {
        const ulonglong2* ep = reinterpret_cast<const ulonglong2*>(es + a * HSIZE);
        ull a0 = 0ULL, a1 = 0ULL, b0 = 0ULL, b1 = 0ULL;
        #pragma unroll
        for (int j = 0; j < 4; j++) {
            ulonglong2 ev = ep[j];
            a0 = ffma2(q0[2 * j], ev.x, a0);
            a1 = ffma2(q0[2 * j + 1], ev.y, a1);
            b0 = ffma2(q1[2 * j], ev.x, b0);
            b1 = ffma2(q1[2 * j + 1], ev.y, b1);
        }
        qe70[a] = hsum2(a0, a1);
        qe71[a] = hsum2(b0, b1);
    }

    const bool axis_i = (head < 4);

    // --- fused streaming pass: score -> exp -> PV ---
    float sum0 = 0.f, sum1 = 0.f;
    ull o0[8], o1[8];
    #pragma unroll
    for (int j = 0; j < 8; j++) { o0[j] = 0ULL; o1[j] = 0ULL; }

    #pragma unroll
    for (int rr = 0; rr < 8; rr++) {
        #pragma unroll
        for (int c = 0; c < 7; c++) {
            int pos = (2 * tyy + rr) * HALO + px + c;
            ulonglong2 kv[4], vv[4];
            #pragma unroll
            for (int j = 0; j < 4; j++) {
                kv[j] = *reinterpret_cast<const ulonglong2*>(&k4[j * 484 + pos]);
                vv[j] = *reinterpret_cast<const ulonglong2*>(&v4[j * 484 + pos]);
            }
            if (rr < 7) {
                ull a0 = 0ULL, a1 = 0ULL;
                #pragma unroll
                for (int j = 0; j < 4; j++) {
                    a0 = ffma2(q0[2 * j], kv[j].x, a0);
                    a1 = ffma2(q0[2 * j + 1], kv[j].y, a1);
                }
                float s = hsum2(a0, a1) + (axis_i ? qe70[rr] : qe70[c]);
                float p = __expf(s);
                sum0 += p;
                ull w2 = pack2(p);
                #pragma unroll
                for (int j = 0; j < 4; j++) {
                    o0[2 * j] = ffma2(w2, vv[j].x, o0[2 * j]);
                    o0[2 * j + 1] = ffma2(w2, vv[j].y, o0[2 * j + 1]);
                }
            }
            if (rr >= 1) {
                ull a0 = 0ULL, a1 = 0ULL;
                #pragma unroll
                for (int j = 0; j < 4; j++) {
                    a0 = ffma2(q1[2 * j], kv[j].x, a0);
                    a1 = ffma2(q1[2 * j + 1], kv[j].y, a1);
                }
                float s = hsum2(a0, a1) + (axis_i ? qe71[rr - 1] : qe71[c]);
                float p = __expf(s);
                sum1 += p;
                ull w2 = pack2(p);
                #pragma unroll
                for (int j = 0; j < 4; j++) {
                    o1[2 * j] = ffma2(w2, vv[j].x, o1[2 * j]);
                    o1[2 * j + 1] = ffma2(w2, vv[j].y, o1[2 * j + 1]);
                }
            }
        }
    }

    float inv0 = 1.f / sum0, inv1 = 1.f / sum1;
    float* op0 = out + poff0;
    float* op1 = out + poff1;
    #pragma unroll
    for (int j = 0; j < 4; j++) {
        float l0, h0, l1, h1;
        unpack2(o0[2 * j], l0, h0);
        unpack2(o0[2 * j + 1], l1, h1);
        float4 r0 = make_float4(l0 * inv0, h0 * inv0, l1 * inv0, h1 * inv0);
        reinterpret_cast<float4*>(op0)[j] = r0;
        unpack2(o1[2 * j], l0, h0);
        unpack2(o1[2 * j + 1], l1, h1);
        float4 r1 = make_float4(l0 * inv1, h0 * inv1, l1 * inv1, h1 * inv1);
        reinterpret_cast<float4*>(op1)[j] = r1;
    }
}

// ---------------------------------------------------------------------------
extern "C" void kernel_launch(void* const* d_in, const int* in_sizes, int n_in,
                              void* d_out, int out_size)
{
    const float* x  = (const float*)d_in[0];
    const float* Wq = (const float*)d_in[1];
    const float* bq = (const float*)d_in[2];
    const float* Wk = (const float*)d_in[3];
    const float* bk = (const float*)d_in[4];
    const float* Wv = (const float*)d_in[5];
    const float* bv = (const float*)d_in[6];
    const float* e0 = (const float*)d_in[7];
    const float* e1 = (const float*)d_in[8];
    float* out = (float*)d_out;

    const int smem_qkv = (64 * XPAD + 64 * 128) * 4;        // ~49.2 KB
    const int smem_attn = 8 * 484 * 16 + 7 * HSIZE * 4;     // 62400 B

    cudaFuncSetAttribute(qkv_kernel,
        cudaFuncAttributeMaxDynamicSharedMemorySize, smem_qkv);
    cudaFuncSetAttribute(attn_kernel,
        cudaFuncAttributeMaxDynamicSharedMemorySize, smem_attn);

    qkv_kernel<<<dim3(NPIX / 64, 3), 256, smem_qkv>>>(x, Wq, bq, Wk, bk, Wv, bv);
    attn_kernel<<<dim3(16, HEADS, 4), 128, smem_attn>>>(out, e0, e1);
}